// round 7
// baseline (speedup 1.0000x reference)
#include <cuda_runtime.h>
#include <cuda_bf16.h>
#include <math.h>

// ---------------- problem constants ----------------
#define BB    64
#define P0    729
#define CC    1152
#define HH    3584
#define HEADS 16
#define HD    72          // CC / HEADS
#define TT    128         // target tokens
#define MROWS (BB*TT)     // 8192

// ---------------- scratch (device globals; no cudaMalloc allowed) -------------
__device__ float g_xa[BB*P0*CC];
__device__ float g_xb[BB*P0*CC];
__device__ float g_sa[BB*P0];
__device__ float g_sb[BB*P0];
__device__ float g_metric[BB*P0*HD];
__device__ float g_nodemax[BB*384];
__device__ int   g_nodeidx[BB*384];
__device__ int   g_edgeidx[BB*384];
__device__ float g_h[(long)MROWS*HH];

__device__ __forceinline__ float* xbuf(int s){ return s ? g_xb : g_xa; }
__device__ __forceinline__ float* sbuf(int s){ return s ? g_sb : g_sa; }

// 3-way bf16 split (BF16x9 FP32-emulation operand decomposition).
// hi = bf16_rn(a); mid = bf16_rn(a-hi); lo = bf16_rn(a-hi-mid).
// All residual subtractions are exact in f32.
__device__ __forceinline__ void bf16split3(float a, float& h, float& m, float& l){
    h = __bfloat162float(__float2bfloat16_rn(a));
    float r1 = __fadd_rn(a, -h);
    m = __bfloat162float(__float2bfloat16_rn(r1));
    float r2 = __fadd_rn(r1, -m);
    l = __bfloat162float(__float2bfloat16_rn(r2));
}

// ---------------- elementwise: x + spatial_pos (IEEE rn add) ----------------
__global__ void k_addpos(const float* __restrict__ x, const float* __restrict__ pos){
    long i = (long)blockIdx.x * blockDim.x + threadIdx.x;
    const long n = (long)BB*P0*CC;
    if (i < n){
        int pc = (int)(i % ((long)P0*CC));
        g_xa[i] = __fadd_rn(x[i], pos[pc]);
    }
}

__global__ void k_initsize(){
    int i = blockIdx.x*blockDim.x + threadIdx.x;
    if (i < BB*P0) g_sa[i] = 1.0f;
}

// ---------------- metric: head-mean + L2 normalize (f32, warp per token) ------
__global__ void k_metric(int ssel, int t){
    int gw = blockIdx.x*4 + (threadIdx.x >> 5);   // token index b*t + i
    if (gw >= BB*t) return;
    int lane = threadIdx.x & 31;
    const float* x = xbuf(ssel) + (long)gw*CC;

    float m0 = 0.f, m1 = 0.f, m2 = 0.f;
    #pragma unroll
    for (int h = 0; h < HEADS; h++){
        m0 = __fadd_rn(m0, x[h*HD + lane]);
        m1 = __fadd_rn(m1, x[h*HD + lane + 32]);
    }
    m0 = __fmul_rn(m0, 0.0625f);
    m1 = __fmul_rn(m1, 0.0625f);
    if (lane < 8){
        #pragma unroll
        for (int h = 0; h < HEADS; h++) m2 = __fadd_rn(m2, x[h*HD + lane + 64]);
        m2 = __fmul_rn(m2, 0.0625f);
    }

    float acc = __fmaf_rn(m0, m0, 0.0f);
    acc = __fmaf_rn(m1, m1, acc);
    if (lane < 8) acc = __fmaf_rn(m2, m2, acc);
    #pragma unroll
    for (int off = 16; off > 0; off >>= 1)
        acc = __fadd_rn(acc, __shfl_down_sync(0xffffffffu, acc, off));
    float nrm = __fsqrt_rn(__shfl_sync(0xffffffffu, acc, 0));

    float* Mo = g_metric + (long)gw*HD;
    Mo[lane]      = __fdiv_rn(m0, nrm);
    Mo[lane + 32] = __fdiv_rn(m1, nrm);
    if (lane < 8) Mo[lane + 64] = __fdiv_rn(m2, nrm);
}

// ---------------- scores: BF16x9-emulated dot, max/argmax over odd tokens -----
// cuBLAS-13/GB300 FP32-emulation model: a,b each split into 3 bf16 limbs;
// 9 partial products (exact in f32); each of the 9 classes K-reduced in its own
// f32 accumulator (ascending k); classes combined least->most significant.
// one block per (b, even-token i), 128 threads
__global__ void k_scores(int t, int na, int nb){
    int bid = blockIdx.x;
    int b = bid / na, i = bid % na;
    const float* M = g_metric + (long)b*t*HD;
    __shared__ float ah[HD], am[HD], al[HD];
    int tid = threadIdx.x;
    if (tid < HD){
        float av = M[(long)(2*i)*HD + tid];
        float h, m, l; bf16split3(av, h, m, l);
        ah[tid] = h; am[tid] = m; al[tid] = l;
    }
    __syncthreads();
    float bv = -2.0f; int bi = 0x7fffffff;
    for (int j = tid; j < nb; j += blockDim.x){
        const float* br = M + (long)(2*j+1)*HD;
        float s_ll = 0.f, s_lm = 0.f, s_ml = 0.f;
        float s_lh = 0.f, s_mm = 0.f, s_hl = 0.f;
        float s_mh = 0.f, s_hm = 0.f, s_hh = 0.f;
        #pragma unroll 8
        for (int k = 0; k < HD; k++){
            float bh, bm, bl; bf16split3(br[k], bh, bm, bl);
            float Ah = ah[k], Am = am[k], Al = al[k];
            s_ll = __fmaf_rn(Al, bl, s_ll);
            s_lm = __fmaf_rn(Al, bm, s_lm);
            s_ml = __fmaf_rn(Am, bl, s_ml);
            s_lh = __fmaf_rn(Al, bh, s_lh);
            s_mm = __fmaf_rn(Am, bm, s_mm);
            s_hl = __fmaf_rn(Ah, bl, s_hl);
            s_mh = __fmaf_rn(Am, bh, s_mh);
            s_hm = __fmaf_rn(Ah, bm, s_hm);
            s_hh = __fmaf_rn(Ah, bh, s_hh);
        }
        // combine ascending significance
        float acc = s_ll;
        acc = __fadd_rn(acc, s_lm);
        acc = __fadd_rn(acc, s_ml);
        acc = __fadd_rn(acc, s_lh);
        acc = __fadd_rn(acc, s_mm);
        acc = __fadd_rn(acc, s_hl);
        acc = __fadd_rn(acc, s_mh);
        acc = __fadd_rn(acc, s_hm);
        acc = __fadd_rn(acc, s_hh);
        if (acc > bv){ bv = acc; bi = j; }   // j ascending -> first max wins ties
    }
    __shared__ float sv[128]; __shared__ int si[128];
    sv[tid] = bv; si[tid] = bi;
    __syncthreads();
    for (int s = 64; s > 0; s >>= 1){
        if (tid < s){
            if (sv[tid+s] > sv[tid] || (sv[tid+s] == sv[tid] && si[tid+s] < si[tid])){
                sv[tid] = sv[tid+s]; si[tid] = si[tid+s];
            }
        }
        __syncthreads();
    }
    if (tid == 0){ g_nodemax[b*384+i] = sv[0]; g_nodeidx[b*384+i] = si[0]; }
}

// ---------------- bitonic sort: descending by value, ascending index on ties ----
__global__ void k_sort(int n){
    int b = blockIdx.x, tid = threadIdx.x, npad = blockDim.x;
    extern __shared__ float smem[];
    float* v  = smem;
    int*   id = (int*)(smem + npad);
    v[tid]  = (tid < n) ? g_nodemax[b*384+tid] : -3.4e38f;
    id[tid] = (tid < n) ? tid : 0x7fffffff;
    __syncthreads();
    for (int k = 2; k <= npad; k <<= 1){
        for (int j = k >> 1; j > 0; j >>= 1){
            int ixj = tid ^ j;
            if (ixj > tid){
                bool up = ((tid & k) == 0);
                bool before = (v[tid] > v[ixj]) || (v[tid] == v[ixj] && id[tid] < id[ixj]);
                if (up ? !before : before){
                    float tv = v[tid]; v[tid] = v[ixj]; v[ixj] = tv;
                    int   ti = id[tid]; id[tid] = id[ixj]; id[ixj] = ti;
                }
            }
            __syncthreads();
        }
    }
    if (tid < n) g_edgeidx[b*384+tid] = id[tid];
}

// ---------------- unmerged tokens: round((x*s)/s) ----------------
__global__ void k_unm(int ssel, int dsel, int t, int tn, int r, int unm){
    int bid = blockIdx.x;
    int b = bid / unm, u = bid % unm;
    int e = g_edgeidx[b*384 + r + u];        // even-token index
    const float* xs = xbuf(ssel) + ((long)b*t + 2*e)*CC;
    float*       xd = xbuf(dsel) + ((long)b*tn + u)*CC;
    float s = sbuf(ssel)[(long)b*t + 2*e];
    for (int d = threadIdx.x; d < CC; d += blockDim.x)
        xd[d] = __fdiv_rn(__fmul_rn(xs[d], s), s);
    if (threadIdx.x == 0) sbuf(dsel)[(long)b*tn + u] = s;
}

// ---------------- destination merge: ordered gather (deterministic) ----------
__global__ void k_dst(int ssel, int dsel, int t, int tn, int nb, int r, int unm){
    int bid = blockIdx.x;
    int b = bid / nb, j = bid % nb;
    __shared__ int   se[368];
    __shared__ int   sn[368];
    __shared__ int   match[368];
    __shared__ float msz[368];
    __shared__ int   nm;
    __shared__ float tsz, osz;
    const float* ss = sbuf(ssel) + (long)b*t;
    for (int k = threadIdx.x; k < r; k += blockDim.x){
        int s = g_edgeidx[b*384+k];
        se[k] = s;
        sn[k] = g_nodeidx[b*384+s];
    }
    __syncthreads();
    if (threadIdx.x == 0){
        int c = 0;
        float os = ss[2*j+1];
        float ts = os;
        for (int k = 0; k < r; k++){
            if (sn[k] == j){
                int s = se[k];
                float sz = ss[2*s];
                match[c] = s; msz[c] = sz;
                ts = __fadd_rn(ts, sz);
                c++;
            }
        }
        nm = c; tsz = ts; osz = os;
    }
    __syncthreads();
    const float* xs = xbuf(ssel) + (long)b*t*CC;
    float*       xd = xbuf(dsel) + ((long)b*tn + unm + j)*CC;
    int lnm = nm; float ltsz = tsz, losz = osz;
    for (int d = threadIdx.x; d < CC; d += blockDim.x){
        float acc = __fmul_rn(xs[(long)(2*j+1)*CC + d], losz);
        for (int m = 0; m < lnm; m++)
            acc = __fadd_rn(acc, __fmul_rn(xs[(long)(2*match[m])*CC + d], msz[m]));
        xd[d] = __fdiv_rn(acc, ltsz);
    }
    if (threadIdx.x == 0) sbuf(dsel)[(long)b*tn + unm + j] = ltsz;
}

// ---------------- SGEMM: 128x128x8 tiles, 8x8 per thread ----------------
__device__ __forceinline__ void sgemm_body(
    const float* __restrict__ A, const float* __restrict__ Bm,
    const float* __restrict__ bias, float* __restrict__ Cm,
    int Ndim, int Kdim, bool gelu)
{
    __shared__ __align__(16) float As[8][128];
    __shared__ __align__(16) float Bs[8][128];
    int bx = blockIdx.x, by = blockIdx.y;
    int tid = threadIdx.x;
    int tx = tid & 15, ty = tid >> 4;
    const float* Ab = A  + (long)by*128*Kdim;
    const float* Bb = Bm + (long)bx*128;

    float acc[8][8];
    #pragma unroll
    for (int i = 0; i < 8; i++)
        #pragma unroll
        for (int j = 0; j < 8; j++) acc[i][j] = 0.f;

    int arow = tid >> 1, acol = (tid & 1) * 4;
    int brow = tid >> 5, bcol = (tid & 31) * 4;

    for (int k0 = 0; k0 < Kdim; k0 += 8){
        float4 av = *(const float4*)(Ab + (long)arow*Kdim + k0 + acol);
        As[acol+0][arow] = av.x; As[acol+1][arow] = av.y;
        As[acol+2][arow] = av.z; As[acol+3][arow] = av.w;
        float4 bv = *(const float4*)(Bb + (long)(k0+brow)*Ndim + bcol);
        *(float4*)&Bs[brow][bcol] = bv;
        __syncthreads();
        #pragma unroll
        for (int k = 0; k < 8; k++){
            float ar[8], br[8];
            #pragma unroll
            for (int i = 0; i < 8; i++) ar[i] = As[k][ty*8+i];
            #pragma unroll
            for (int j = 0; j < 8; j++) br[j] = Bs[k][tx*8+j];
            #pragma unroll
            for (int i = 0; i < 8; i++)
                #pragma unroll
                for (int j = 0; j < 8; j++) acc[i][j] = __fmaf_rn(ar[i], br[j], acc[i][j]);
        }
        __syncthreads();
    }

    int col0 = bx*128 + tx*8;
    #pragma unroll
    for (int i = 0; i < 8; i++){
        long row = (long)by*128 + ty*8 + i;
        float4 o0, o1;
        float* po0 = &o0.x; float* po1 = &o1.x;
        #pragma unroll
        for (int j = 0; j < 4; j++){
            float v = __fadd_rn(acc[i][j], bias[col0+j]);
            if (gelu) v = 0.5f*v*(1.0f + erff(v*0.70710678118654752f));
            po0[j] = v;
        }
        #pragma unroll
        for (int j = 0; j < 4; j++){
            float v = __fadd_rn(acc[i][4+j], bias[col0+4+j]);
            if (gelu) v = 0.5f*v*(1.0f + erff(v*0.70710678118654752f));
            po1[j] = v;
        }
        *(float4*)(Cm + row*Ndim + col0)     = o0;
        *(float4*)(Cm + row*Ndim + col0 + 4) = o1;
    }
}

__global__ __launch_bounds__(256) void k_gemm1(const float* __restrict__ w1,
                                               const float* __restrict__ b1){
    sgemm_body(g_xb, w1, b1, g_h, HH, CC, true);
}

__global__ __launch_bounds__(256) void k_gemm2(const float* __restrict__ w2,
                                               const float* __restrict__ b2,
                                               float* __restrict__ out){
    sgemm_body(g_h, w2, b2, out, HH, HH, false);
}

// ---------------- launcher ----------------
extern "C" void kernel_launch(void* const* d_in, const int* in_sizes, int n_in,
                              void* d_out, int out_size){
    const float* x   = (const float*)d_in[0];
    const float* pos = (const float*)d_in[1];
    const float* w1  = (const float*)d_in[2];
    const float* b1  = (const float*)d_in[3];
    const float* w2  = (const float*)d_in[4];
    const float* b2  = (const float*)d_in[5];
    float* out = (float*)d_out;

    {
        long n = (long)BB*P0*CC;
        k_addpos<<<(unsigned)((n + 255)/256), 256>>>(x, pos);
        k_initsize<<<(BB*P0 + 255)/256, 256>>>();
    }

    // merge schedule: 729 -> 365 -> 183 -> 128, r = {364, 182, 55}
    const int T[4] = {729, 365, 183, 128};
    const int R[3] = {364, 182, 55};
    int ssel = 0;
    for (int it = 0; it < 3; it++){
        int t = T[it], tn = T[it+1];
        int na = (t + 1) / 2, nb = t / 2;
        int r = R[it], unm = na - r;
        int dsel = 1 - ssel;
        int npad = 1; while (npad < na) npad <<= 1;

        k_metric<<<(BB*t + 3)/4, 128>>>(ssel, t);
        k_scores<<<BB*na, 128>>>(t, na, nb);
        k_sort<<<BB, npad, npad*8>>>(na);
        k_unm<<<BB*unm, 128>>>(ssel, dsel, t, tn, r, unm);
        k_dst<<<BB*nb, 128>>>(ssel, dsel, t, tn, nb, r, unm);
        ssel = dsel;
    }
    // after 3 iterations ssel == 1 (g_xb holds 64x128x1152 merged tokens)

    dim3 blk(256);
    dim3 g1(HH/128, MROWS/128);
    k_gemm1<<<g1, blk>>>(w1, b1);
    k_gemm2<<<g1, blk>>>(w2, b2, out);
}

// round 12
// speedup vs baseline: 1.6492x; 1.6492x over previous
#include <cuda_runtime.h>
#include <cuda_bf16.h>
#include <math.h>
#include <stdint.h>

// ---------------- problem constants ----------------
#define BB    64
#define P0    729
#define CC    1152
#define HH    3584
#define HEADS 16
#define HD    72
#define TT    128
#define MROWS (BB*TT)     // 8192

// ---------------- scratch (device globals) ----------------
__device__ float g_xa[BB*P0*CC];
__device__ float g_xb[BB*P0*CC];
__device__ float g_sa[BB*P0];
__device__ float g_sb[BB*P0];
__device__ float g_metric[BB*P0*HD];
__device__ float g_nodemax[BB*384];
__device__ int   g_nodeidx[BB*384];
__device__ int   g_edgeidx[BB*384];
// bf16 limb buffers for tensor-core GEMMs
__device__ __align__(16) unsigned short g_a1h[(long)MROWS*CC];
__device__ __align__(16) unsigned short g_a1l[(long)MROWS*CC];
__device__ __align__(16) unsigned short g_a2h[(long)MROWS*HH];
__device__ __align__(16) unsigned short g_a2l[(long)MROWS*HH];
__device__ __align__(16) unsigned short g_b1h[(long)HH*CC];
__device__ __align__(16) unsigned short g_b1l[(long)HH*CC];
__device__ __align__(16) unsigned short g_b2h[(long)HH*HH];
__device__ __align__(16) unsigned short g_b2l[(long)HH*HH];

__device__ __forceinline__ float* xbuf(int s){ return s ? g_xb : g_xa; }
__device__ __forceinline__ float* sbuf(int s){ return s ? g_sb : g_sa; }

// ---------------- portable PTX helpers (sm_80+; legal on compute_103) ----------
__device__ __forceinline__ uint32_t smem_u32(const void* p){
    uint32_t a;
    asm("{ .reg .u64 t; cvta.to.shared.u64 t, %1; cvt.u32.u64 %0, t; }" : "=r"(a) : "l"(p));
    return a;
}
__device__ __forceinline__ void cp16(uint32_t dst, const void* src){
    asm volatile("cp.async.cg.shared.global [%0], [%1], 16;" :: "r"(dst), "l"(src) : "memory");
}
#define CP_COMMIT() asm volatile("cp.async.commit_group;" ::: "memory")
#define CP_WAIT(n)  asm volatile("cp.async.wait_group %0;" :: "n"(n) : "memory")

__device__ __forceinline__ void ldsm_x4(uint32_t& r0, uint32_t& r1, uint32_t& r2, uint32_t& r3, uint32_t addr){
    asm volatile("ldmatrix.sync.aligned.m8n8.x4.shared.b16 {%0,%1,%2,%3}, [%4];"
        : "=r"(r0), "=r"(r1), "=r"(r2), "=r"(r3) : "r"(addr));
}
__device__ __forceinline__ void ldsm_x2(uint32_t& r0, uint32_t& r1, uint32_t addr){
    asm volatile("ldmatrix.sync.aligned.m8n8.x2.shared.b16 {%0,%1}, [%2];"
        : "=r"(r0), "=r"(r1) : "r"(addr));
}
__device__ __forceinline__ void mma16816(float* d, const uint32_t* a, const uint32_t* b){
    asm volatile("mma.sync.aligned.m16n8k16.row.col.f32.bf16.bf16.f32 "
        "{%0,%1,%2,%3}, {%4,%5,%6,%7}, {%8,%9}, {%0,%1,%2,%3};"
        : "+f"(d[0]), "+f"(d[1]), "+f"(d[2]), "+f"(d[3])
        : "r"(a[0]), "r"(a[1]), "r"(a[2]), "r"(a[3]), "r"(b[0]), "r"(b[1]));
}

// bf16 2-way split (GEMM limbs)
__device__ __forceinline__ void bf16split2(float a, unsigned short& h, unsigned short& l){
    __nv_bfloat16 hb = __float2bfloat16_rn(a);
    float hf = __bfloat162float(hb);
    __nv_bfloat16 lb = __float2bfloat16_rn(__fadd_rn(a, -hf));
    h = *(unsigned short*)&hb; l = *(unsigned short*)&lb;
}
// 3-way (decision scores; BF16x9 reference model)
__device__ __forceinline__ void bf16split3(float a, float& h, float& m, float& l){
    h = __bfloat162float(__float2bfloat16_rn(a));
    float r1 = __fadd_rn(a, -h);
    m = __bfloat162float(__float2bfloat16_rn(r1));
    float r2 = __fadd_rn(r1, -m);
    l = __bfloat162float(__float2bfloat16_rn(r2));
}

// ---------------- elementwise ----------------
__global__ void k_addpos(const float* __restrict__ x, const float* __restrict__ pos){
    long i = (long)blockIdx.x * blockDim.x + threadIdx.x;
    const long n = (long)BB*P0*CC;
    if (i < n){
        int pc = (int)(i % ((long)P0*CC));
        g_xa[i] = __fadd_rn(x[i], pos[pc]);
    }
}
__global__ void k_initsize(){
    int i = blockIdx.x*blockDim.x + threadIdx.x;
    if (i < BB*P0) g_sa[i] = 1.0f;
}

// ---------------- metric (frozen, passing) ----------------
__global__ void k_metric(int ssel, int t){
    int gw = blockIdx.x*4 + (threadIdx.x >> 5);
    if (gw >= BB*t) return;
    int lane = threadIdx.x & 31;
    const float* x = xbuf(ssel) + (long)gw*CC;
    float m0 = 0.f, m1 = 0.f, m2 = 0.f;
    #pragma unroll
    for (int h = 0; h < HEADS; h++){
        m0 = __fadd_rn(m0, x[h*HD + lane]);
        m1 = __fadd_rn(m1, x[h*HD + lane + 32]);
    }
    m0 = __fmul_rn(m0, 0.0625f);
    m1 = __fmul_rn(m1, 0.0625f);
    if (lane < 8){
        #pragma unroll
        for (int h = 0; h < HEADS; h++) m2 = __fadd_rn(m2, x[h*HD + lane + 64]);
        m2 = __fmul_rn(m2, 0.0625f);
    }
    float acc = __fmaf_rn(m0, m0, 0.0f);
    acc = __fmaf_rn(m1, m1, acc);
    if (lane < 8) acc = __fmaf_rn(m2, m2, acc);
    #pragma unroll
    for (int off = 16; off > 0; off >>= 1)
        acc = __fadd_rn(acc, __shfl_down_sync(0xffffffffu, acc, off));
    float nrm = __fsqrt_rn(__shfl_sync(0xffffffffu, acc, 0));
    float* Mo = g_metric + (long)gw*HD;
    Mo[lane]      = __fdiv_rn(m0, nrm);
    Mo[lane + 32] = __fdiv_rn(m1, nrm);
    if (lane < 8) Mo[lane + 64] = __fdiv_rn(m2, nrm);
}

// ---------------- scores: BF16x9-emulated dot (frozen, passing) ----------------
__global__ void k_scores(int t, int na, int nb){
    int bid = blockIdx.x;
    int b = bid / na, i = bid % na;
    const float* M = g_metric + (long)b*t*HD;
    __shared__ float ah[HD], am[HD], al[HD];
    int tid = threadIdx.x;
    if (tid < HD){
        float av = M[(long)(2*i)*HD + tid];
        float h, m, l; bf16split3(av, h, m, l);
        ah[tid] = h; am[tid] = m; al[tid] = l;
    }
    __syncthreads();
    float bv = -2.0f; int bi = 0x7fffffff;
    for (int j = tid; j < nb; j += blockDim.x){
        const float* br = M + (long)(2*j+1)*HD;
        float s_ll=0.f,s_lm=0.f,s_ml=0.f,s_lh=0.f,s_mm=0.f,s_hl=0.f,s_mh=0.f,s_hm=0.f,s_hh=0.f;
        #pragma unroll 8
        for (int k = 0; k < HD; k++){
            float bh, bm, bl; bf16split3(br[k], bh, bm, bl);
            float Ah = ah[k], Am = am[k], Al = al[k];
            s_ll = __fmaf_rn(Al, bl, s_ll);
            s_lm = __fmaf_rn(Al, bm, s_lm);
            s_ml = __fmaf_rn(Am, bl, s_ml);
            s_lh = __fmaf_rn(Al, bh, s_lh);
            s_mm = __fmaf_rn(Am, bm, s_mm);
            s_hl = __fmaf_rn(Ah, bl, s_hl);
            s_mh = __fmaf_rn(Am, bh, s_mh);
            s_hm = __fmaf_rn(Ah, bm, s_hm);
            s_hh = __fmaf_rn(Ah, bh, s_hh);
        }
        float acc = s_ll;
        acc = __fadd_rn(acc, s_lm);
        acc = __fadd_rn(acc, s_ml);
        acc = __fadd_rn(acc, s_lh);
        acc = __fadd_rn(acc, s_mm);
        acc = __fadd_rn(acc, s_hl);
        acc = __fadd_rn(acc, s_mh);
        acc = __fadd_rn(acc, s_hm);
        acc = __fadd_rn(acc, s_hh);
        if (acc > bv){ bv = acc; bi = j; }
    }
    __shared__ float sv[128]; __shared__ int si[128];
    sv[tid] = bv; si[tid] = bi;
    __syncthreads();
    for (int s = 64; s > 0; s >>= 1){
        if (tid < s){
            if (sv[tid+s] > sv[tid] || (sv[tid+s] == sv[tid] && si[tid+s] < si[tid])){
                sv[tid] = sv[tid+s]; si[tid] = si[tid+s];
            }
        }
        __syncthreads();
    }
    if (tid == 0){ g_nodemax[b*384+i] = sv[0]; g_nodeidx[b*384+i] = si[0]; }
}

// ---------------- sort / unm / dst (frozen, passing) ----------------
__global__ void k_sort(int n){
    int b = blockIdx.x, tid = threadIdx.x, npad = blockDim.x;
    extern __shared__ float smemf[];
    float* v  = smemf;
    int*   id = (int*)(smemf + npad);
    v[tid]  = (tid < n) ? g_nodemax[b*384+tid] : -3.4e38f;
    id[tid] = (tid < n) ? tid : 0x7fffffff;
    __syncthreads();
    for (int k = 2; k <= npad; k <<= 1){
        for (int j = k >> 1; j > 0; j >>= 1){
            int ixj = tid ^ j;
            if (ixj > tid){
                bool up = ((tid & k) == 0);
                bool before = (v[tid] > v[ixj]) || (v[tid] == v[ixj] && id[tid] < id[ixj]);
                if (up ? !before : before){
                    float tv = v[tid]; v[tid] = v[ixj]; v[ixj] = tv;
                    int   ti = id[tid]; id[tid] = id[ixj]; id[ixj] = ti;
                }
            }
            __syncthreads();
        }
    }
    if (tid < n) g_edgeidx[b*384+tid] = id[tid];
}

__global__ void k_unm(int ssel, int dsel, int t, int tn, int r, int unm){
    int bid = blockIdx.x;
    int b = bid / unm, u = bid % unm;
    int e = g_edgeidx[b*384 + r + u];
    const float* xs = xbuf(ssel) + ((long)b*t + 2*e)*CC;
    float*       xd = xbuf(dsel) + ((long)b*tn + u)*CC;
    float s = sbuf(ssel)[(long)b*t + 2*e];
    for (int d = threadIdx.x; d < CC; d += blockDim.x)
        xd[d] = __fdiv_rn(__fmul_rn(xs[d], s), s);
    if (threadIdx.x == 0) sbuf(dsel)[(long)b*tn + u] = s;
}

__global__ void k_dst(int ssel, int dsel, int t, int tn, int nb, int r, int unm){
    int bid = blockIdx.x;
    int b = bid / nb, j = bid % nb;
    __shared__ int   se[368];
    __shared__ int   sn[368];
    __shared__ int   match[368];
    __shared__ float msz[368];
    __shared__ int   nm;
    __shared__ float tsz, osz;
    const float* ss = sbuf(ssel) + (long)b*t;
    for (int k = threadIdx.x; k < r; k += blockDim.x){
        int s = g_edgeidx[b*384+k];
        se[k] = s;
        sn[k] = g_nodeidx[b*384+s];
    }
    __syncthreads();
    if (threadIdx.x == 0){
        int c = 0;
        float os = ss[2*j+1];
        float ts = os;
        for (int k = 0; k < r; k++){
            if (sn[k] == j){
                int s = se[k];
                float sz = ss[2*s];
                match[c] = s; msz[c] = sz;
                ts = __fadd_rn(ts, sz);
                c++;
            }
        }
        nm = c; tsz = ts; osz = os;
    }
    __syncthreads();
    const float* xs = xbuf(ssel) + (long)b*t*CC;
    float*       xd = xbuf(dsel) + ((long)b*tn + unm + j)*CC;
    int lnm = nm; float ltsz = tsz, losz = osz;
    for (int d = threadIdx.x; d < CC; d += blockDim.x){
        float acc = __fmul_rn(xs[(long)(2*j+1)*CC + d], losz);
        for (int m = 0; m < lnm; m++)
            acc = __fadd_rn(acc, __fmul_rn(xs[(long)(2*match[m])*CC + d], msz[m]));
        xd[d] = __fdiv_rn(acc, ltsz);
    }
    if (threadIdx.x == 0) sbuf(dsel)[(long)b*tn + unm + j] = ltsz;
}

// ---------------- prep: split merged x into bf16 hi/lo ----------------
__global__ void k_splitx(){
    long i = (long)blockIdx.x * blockDim.x + threadIdx.x;
    const long n = (long)MROWS*CC;
    if (i < n){
        unsigned short h, l;
        bf16split2(g_xb[i], h, l);
        g_a1h[i] = h; g_a1l[i] = l;
    }
}

// ---------------- prep: transpose+split weights W[K,N] -> Bh/Bl [N,K] ----------------
__global__ void k_splitw(const float* __restrict__ W,
                         unsigned short* __restrict__ Bh, unsigned short* __restrict__ Bl,
                         int K, int N){
    __shared__ float tile[32][33];
    int kb = blockIdx.y*32, nb = blockIdx.x*32;
    int tx = threadIdx.x & 31, ty = threadIdx.x >> 5;
    for (int i = ty; i < 32; i += 8)
        tile[i][tx] = W[(long)(kb+i)*N + nb + tx];
    __syncthreads();
    for (int i = ty; i < 32; i += 8){
        float v = tile[tx][i];
        unsigned short h, l;
        bf16split2(v, h, l);
        long o = (long)(nb+i)*K + kb + tx;
        Bh[o] = h; Bl[o] = l;
    }
}

// ---------------- HMMA bf16x3 GEMM (portable mma.sync path) ----------------
// C[M,N] = A[M,K] x B[N,K]^T ; A,B bf16 hi/lo limbs; f32 accum.
// CTA 128x128, K-chunk 32; 8 warps 2(M)x4(N); warp 64x32 = 4x4 m16n8k16 tiles.
// SMEM rows padded to 40 bf16 (80B) -> conflict-free ldmatrix (20r mod 32 distinct).
#define RS      40
#define TILE_B  (128*RS*2)      // 10240 bytes per operand array
#define BUF_B   (4*TILE_B)      // Ah,Al,Bh,Bl
#define GSMEM   (2*BUF_B)       // 81920 bytes

template<int DO_GELU>
__global__ __launch_bounds__(256) void k_mmagemm(
    const unsigned short* __restrict__ Ah, const unsigned short* __restrict__ Al,
    const unsigned short* __restrict__ Bh, const unsigned short* __restrict__ Bl,
    const float* __restrict__ bias, int K,
    float* __restrict__ Cf,
    unsigned short* __restrict__ C2h, unsigned short* __restrict__ C2l)
{
    extern __shared__ char smemc[];
    uint32_t sb = smem_u32(smemc);
    int tid = threadIdx.x, lane = tid & 31, wid = tid >> 5;
    int wm = wid & 1, wn = wid >> 1;
    long m0 = (long)blockIdx.y*128, n0 = (long)blockIdx.x*128;
    int nc = K / 32;

    float acc[4][4][4];
    #pragma unroll
    for (int a = 0; a < 4; a++)
        #pragma unroll
        for (int b = 0; b < 4; b++)
            #pragma unroll
            for (int c = 0; c < 4; c++) acc[a][b][c] = 0.f;

    const unsigned short* srcs[4] = {Ah, Al, Bh, Bl};
    long r0s[4]; r0s[0] = m0; r0s[1] = m0; r0s[2] = n0; r0s[3] = n0;

    // issue cp.async fill of buffer `buf` with chunk c
    auto load_buf = [&](int buf, int c){
        int k0 = c * 32;
        uint32_t base = sb + buf*BUF_B;
        #pragma unroll
        for (int a = 0; a < 4; a++){
            #pragma unroll
            for (int i = 0; i < 2; i++){
                int idx = tid + i*256;            // 0..511
                int row = idx >> 2, g = idx & 3;  // 128 rows x 4 granules(8 bf16)
                uint32_t dst = base + a*TILE_B + row*80 + g*16;
                cp16(dst, srcs[a] + (r0s[a]+row)*(long)K + k0 + g*8);
            }
        }
    };

    auto comp = [&](int buf){
        uint32_t base   = sb + buf*BUF_B;
        uint32_t baseAh = base,            baseAl = base + TILE_B;
        uint32_t baseBh = base + 2*TILE_B, baseBl = base + 3*TILE_B;
        #pragma unroll
        for (int ks = 0; ks < 2; ks++){
            uint32_t bh[4][2], bl[4][2];
            int bn8 = lane & 7, bg = (lane >> 3) & 1;
            #pragma unroll
            for (int ni = 0; ni < 4; ni++){
                int nrow = wn*32 + ni*8 + bn8;
                uint32_t ab = nrow*80 + (ks*2 + bg)*16;
                ldsm_x2(bh[ni][0], bh[ni][1], baseBh + ab);
                ldsm_x2(bl[ni][0], bl[ni][1], baseBl + ab);
            }
            #pragma unroll
            for (int mi = 0; mi < 4; mi++){
                int arow = wm*64 + mi*16 + (lane & 15);
                int ag = ks*2 + (lane >> 4);
                uint32_t aoff = arow*80 + ag*16;
                uint32_t a_h[4], a_l[4];
                ldsm_x4(a_h[0], a_h[1], a_h[2], a_h[3], baseAh + aoff);
                ldsm_x4(a_l[0], a_l[1], a_l[2], a_l[3], baseAl + aoff);
                #pragma unroll
                for (int ni = 0; ni < 4; ni++){
                    mma16816(acc[mi][ni], a_h, bh[ni]);
                    mma16816(acc[mi][ni], a_h, bl[ni]);
                    mma16816(acc[mi][ni], a_l, bh[ni]);
                }
            }
        }
    };

    load_buf(0, 0); CP_COMMIT();
    for (int c = 0; c < nc; c++){
        if (c + 1 < nc){
            load_buf((c+1) & 1, c+1); CP_COMMIT();
            CP_WAIT(1);
        } else {
            CP_WAIT(0);
        }
        __syncthreads();
        comp(c & 1);
        __syncthreads();
    }

    // epilogue: d-reg mapping of m16n8k16: lane l, reg r:
    // row = base + l/4 + (r>=2)*8 ; col = base + (l%4)*2 + (r&1)
    #pragma unroll
    for (int mi = 0; mi < 4; mi++){
        #pragma unroll
        for (int ni = 0; ni < 4; ni++){
            #pragma unroll
            for (int r = 0; r < 4; r++){
                long m = m0 + wm*64 + mi*16 + (lane >> 2) + ((r >> 1) << 3);
                long n = n0 + wn*32 + ni*8  + ((lane & 3) << 1) + (r & 1);
                float v = __fadd_rn(acc[mi][ni][r], __ldg(bias + n));
                if (DO_GELU){
                    v = 0.5f*v*(1.0f + erff(v*0.70710678118654752f));
                    unsigned short h, l;
                    bf16split2(v, h, l);
                    C2h[m*HH + n] = h; C2l[m*HH + n] = l;
                } else {
                    Cf[m*HH + n] = v;
                }
            }
        }
    }
}

// ---------------- launcher ----------------
extern "C" void kernel_launch(void* const* d_in, const int* in_sizes, int n_in,
                              void* d_out, int out_size){
    const float* x   = (const float*)d_in[0];
    const float* pos = (const float*)d_in[1];
    const float* w1  = (const float*)d_in[2];
    const float* b1  = (const float*)d_in[3];
    const float* w2  = (const float*)d_in[4];
    const float* b2  = (const float*)d_in[5];
    float* out = (float*)d_out;

    void *p_a1h, *p_a1l, *p_a2h, *p_a2l, *p_b1h, *p_b1l, *p_b2h, *p_b2l;
    cudaGetSymbolAddress(&p_a1h, g_a1h); cudaGetSymbolAddress(&p_a1l, g_a1l);
    cudaGetSymbolAddress(&p_a2h, g_a2h); cudaGetSymbolAddress(&p_a2l, g_a2l);
    cudaGetSymbolAddress(&p_b1h, g_b1h); cudaGetSymbolAddress(&p_b1l, g_b1l);
    cudaGetSymbolAddress(&p_b2h, g_b2h); cudaGetSymbolAddress(&p_b2l, g_b2l);

    cudaFuncSetAttribute(k_mmagemm<1>, cudaFuncAttributeMaxDynamicSharedMemorySize, GSMEM);
    cudaFuncSetAttribute(k_mmagemm<0>, cudaFuncAttributeMaxDynamicSharedMemorySize, GSMEM);

    {
        long n = (long)BB*P0*CC;
        k_addpos<<<(unsigned)((n + 255)/256), 256>>>(x, pos);
        k_initsize<<<(BB*P0 + 255)/256, 256>>>();
    }

    // weight prep (independent of merges)
    k_splitw<<<dim3(HH/32, CC/32), 256>>>(w1, (unsigned short*)p_b1h, (unsigned short*)p_b1l, CC, HH);
    k_splitw<<<dim3(HH/32, HH/32), 256>>>(w2, (unsigned short*)p_b2h, (unsigned short*)p_b2l, HH, HH);

    // merge schedule: 729 -> 365 -> 183 -> 128, r = {364, 182, 55}
    const int T[4] = {729, 365, 183, 128};
    const int R[3] = {364, 182, 55};
    int ssel = 0;
    for (int it = 0; it < 3; it++){
        int t = T[it], tn = T[it+1];
        int na = (t + 1) / 2, nb = t / 2;
        int r = R[it], unm = na - r;
        int dsel = 1 - ssel;
        int npad = 1; while (npad < na) npad <<= 1;

        k_metric<<<(BB*t + 3)/4, 128>>>(ssel, t);
        k_scores<<<BB*na, 128>>>(t, na, nb);
        k_sort<<<BB, npad, npad*8>>>(na);
        k_unm<<<BB*unm, 128>>>(ssel, dsel, t, tn, r, unm);
        k_dst<<<BB*nb, 128>>>(ssel, dsel, t, tn, nb, r, unm);
        ssel = dsel;
    }
    // merged tokens now in g_xb (64x128x1152)

    {
        long n = (long)MROWS*CC;
        k_splitx<<<(unsigned)((n + 255)/256), 256>>>();
    }

    dim3 gg(HH/128, MROWS/128);   // 28 x 64
    k_mmagemm<1><<<gg, 256, GSMEM>>>(
        (const unsigned short*)p_a1h, (const unsigned short*)p_a1l,
        (const unsigned short*)p_b1h, (const unsigned short*)p_b1l,
        b1, CC, nullptr,
        (unsigned short*)p_a2h, (unsigned short*)p_a2l);
    k_mmagemm<0><<<gg, 256, GSMEM>>>(
        (const unsigned short*)p_a2h, (const unsigned short*)p_a2l,
        (const unsigned short*)p_b2h, (const unsigned short*)p_b2l,
        b2, HH, out, nullptr, nullptr);
}

// round 13
// speedup vs baseline: 2.1043x; 1.2760x over previous
#include <cuda_runtime.h>
#include <cuda_bf16.h>
#include <cuda_fp16.h>
#include <math.h>
#include <stdint.h>

// ---------------- problem constants ----------------
#define BB    64
#define P0    729
#define CC    1152
#define HH    3584
#define HEADS 16
#define HD    72
#define TT    128
#define MROWS (BB*TT)     // 8192

// ---------------- scratch (device globals) ----------------
__device__ float g_xa[BB*P0*CC];
__device__ float g_xb[BB*P0*CC];
__device__ float g_sa[BB*P0];
__device__ float g_sb[BB*P0];
__device__ float g_metric[BB*P0*HD];
__device__ float g_nodemax[BB*384];
__device__ int   g_nodeidx[BB*384];
__device__ int   g_edgeidx[BB*384];
// fp16 operand buffers for tensor-core GEMMs
__device__ __align__(16) unsigned short g_a1[(long)MROWS*CC];     // A1 fp16
__device__ __align__(16) unsigned short g_a2[(long)MROWS*HH];     // A2 fp16 (gelu out)
__device__ __align__(16) unsigned short g_b1h[(long)HH*CC];       // W1^T hi
__device__ __align__(16) unsigned short g_b1l[(long)HH*CC];       // W1^T lo
__device__ __align__(16) unsigned short g_b2h[(long)HH*HH];
__device__ __align__(16) unsigned short g_b2l[(long)HH*HH];

__device__ __forceinline__ float* xbuf(int s){ return s ? g_xb : g_xa; }
__device__ __forceinline__ float* sbuf(int s){ return s ? g_sb : g_sa; }

// ---------------- portable PTX helpers (sm_80+) ----------------
__device__ __forceinline__ uint32_t smem_u32(const void* p){
    uint32_t a;
    asm("{ .reg .u64 t; cvta.to.shared.u64 t, %1; cvt.u32.u64 %0, t; }" : "=r"(a) : "l"(p));
    return a;
}
__device__ __forceinline__ void cp16(uint32_t dst, const void* src){
    asm volatile("cp.async.cg.shared.global [%0], [%1], 16;" :: "r"(dst), "l"(src) : "memory");
}
#define CP_COMMIT() asm volatile("cp.async.commit_group;" ::: "memory")
#define CP_WAIT(n)  asm volatile("cp.async.wait_group %0;" :: "n"(n) : "memory")

__device__ __forceinline__ void ldsm_x4(uint32_t& r0, uint32_t& r1, uint32_t& r2, uint32_t& r3, uint32_t addr){
    asm volatile("ldmatrix.sync.aligned.m8n8.x4.shared.b16 {%0,%1,%2,%3}, [%4];"
        : "=r"(r0), "=r"(r1), "=r"(r2), "=r"(r3) : "r"(addr));
}
__device__ __forceinline__ void ldsm_x2(uint32_t& r0, uint32_t& r1, uint32_t addr){
    asm volatile("ldmatrix.sync.aligned.m8n8.x2.shared.b16 {%0,%1}, [%2];"
        : "=r"(r0), "=r"(r1) : "r"(addr));
}
__device__ __forceinline__ void mma16816h(float* d, const uint32_t* a, const uint32_t* b){
    asm volatile("mma.sync.aligned.m16n8k16.row.col.f32.f16.f16.f32 "
        "{%0,%1,%2,%3}, {%4,%5,%6,%7}, {%8,%9}, {%0,%1,%2,%3};"
        : "+f"(d[0]), "+f"(d[1]), "+f"(d[2]), "+f"(d[3])
        : "r"(a[0]), "r"(a[1]), "r"(a[2]), "r"(a[3]), "r"(b[0]), "r"(b[1]));
}

// fp16 quantize / 2-way split
__device__ __forceinline__ unsigned short f16q(float a){
    __half h = __float2half_rn(a);
    return *(unsigned short*)&h;
}
__device__ __forceinline__ void f16split2(float a, unsigned short& h, unsigned short& l){
    __half hb = __float2half_rn(a);
    float hf = __half2float(hb);
    __half lb = __float2half_rn(__fadd_rn(a, -hf));
    h = *(unsigned short*)&hb; l = *(unsigned short*)&lb;
}
// 3-way bf16 (decision scores; BF16x9 reference model — FROZEN)
__device__ __forceinline__ void bf16split3(float a, float& h, float& m, float& l){
    h = __bfloat162float(__float2bfloat16_rn(a));
    float r1 = __fadd_rn(a, -h);
    m = __bfloat162float(__float2bfloat16_rn(r1));
    float r2 = __fadd_rn(r1, -m);
    l = __bfloat162float(__float2bfloat16_rn(r2));
}

// ---------------- elementwise ----------------
__global__ void k_addpos(const float* __restrict__ x, const float* __restrict__ pos){
    long i = (long)blockIdx.x * blockDim.x + threadIdx.x;
    const long n = (long)BB*P0*CC;
    if (i < n){
        int pc = (int)(i % ((long)P0*CC));
        g_xa[i] = __fadd_rn(x[i], pos[pc]);
    }
}
__global__ void k_initsize(){
    int i = blockIdx.x*blockDim.x + threadIdx.x;
    if (i < BB*P0) g_sa[i] = 1.0f;
}

// ---------------- metric (frozen, passing) ----------------
__global__ void k_metric(int ssel, int t){
    int gw = blockIdx.x*4 + (threadIdx.x >> 5);
    if (gw >= BB*t) return;
    int lane = threadIdx.x & 31;
    const float* x = xbuf(ssel) + (long)gw*CC;
    float m0 = 0.f, m1 = 0.f, m2 = 0.f;
    #pragma unroll
    for (int h = 0; h < HEADS; h++){
        m0 = __fadd_rn(m0, x[h*HD + lane]);
        m1 = __fadd_rn(m1, x[h*HD + lane + 32]);
    }
    m0 = __fmul_rn(m0, 0.0625f);
    m1 = __fmul_rn(m1, 0.0625f);
    if (lane < 8){
        #pragma unroll
        for (int h = 0; h < HEADS; h++) m2 = __fadd_rn(m2, x[h*HD + lane + 64]);
        m2 = __fmul_rn(m2, 0.0625f);
    }
    float acc = __fmaf_rn(m0, m0, 0.0f);
    acc = __fmaf_rn(m1, m1, acc);
    if (lane < 8) acc = __fmaf_rn(m2, m2, acc);
    #pragma unroll
    for (int off = 16; off > 0; off >>= 1)
        acc = __fadd_rn(acc, __shfl_down_sync(0xffffffffu, acc, off));
    float nrm = __fsqrt_rn(__shfl_sync(0xffffffffu, acc, 0));
    float* Mo = g_metric + (long)gw*HD;
    Mo[lane]      = __fdiv_rn(m0, nrm);
    Mo[lane + 32] = __fdiv_rn(m1, nrm);
    if (lane < 8) Mo[lane + 64] = __fdiv_rn(m2, nrm);
}

// ---------------- scores: BF16x9-emulated dot (frozen, passing) ----------------
__global__ void k_scores(int t, int na, int nb){
    int bid = blockIdx.x;
    int b = bid / na, i = bid % na;
    const float* M = g_metric + (long)b*t*HD;
    __shared__ float ah[HD], am[HD], al[HD];
    int tid = threadIdx.x;
    if (tid < HD){
        float av = M[(long)(2*i)*HD + tid];
        float h, m, l; bf16split3(av, h, m, l);
        ah[tid] = h; am[tid] = m; al[tid] = l;
    }
    __syncthreads();
    float bv = -2.0f; int bi = 0x7fffffff;
    for (int j = tid; j < nb; j += blockDim.x){
        const float* br = M + (long)(2*j+1)*HD;
        float s_ll=0.f,s_lm=0.f,s_ml=0.f,s_lh=0.f,s_mm=0.f,s_hl=0.f,s_mh=0.f,s_hm=0.f,s_hh=0.f;
        #pragma unroll 8
        for (int k = 0; k < HD; k++){
            float bh, bm, bl; bf16split3(br[k], bh, bm, bl);
            float Ah = ah[k], Am = am[k], Al = al[k];
            s_ll = __fmaf_rn(Al, bl, s_ll);
            s_lm = __fmaf_rn(Al, bm, s_lm);
            s_ml = __fmaf_rn(Am, bl, s_ml);
            s_lh = __fmaf_rn(Al, bh, s_lh);
            s_mm = __fmaf_rn(Am, bm, s_mm);
            s_hl = __fmaf_rn(Ah, bl, s_hl);
            s_mh = __fmaf_rn(Am, bh, s_mh);
            s_hm = __fmaf_rn(Ah, bm, s_hm);
            s_hh = __fmaf_rn(Ah, bh, s_hh);
        }
        float acc = s_ll;
        acc = __fadd_rn(acc, s_lm);
        acc = __fadd_rn(acc, s_ml);
        acc = __fadd_rn(acc, s_lh);
        acc = __fadd_rn(acc, s_mm);
        acc = __fadd_rn(acc, s_hl);
        acc = __fadd_rn(acc, s_mh);
        acc = __fadd_rn(acc, s_hm);
        acc = __fadd_rn(acc, s_hh);
        if (acc > bv){ bv = acc; bi = j; }
    }
    __shared__ float sv[128]; __shared__ int si[128];
    sv[tid] = bv; si[tid] = bi;
    __syncthreads();
    for (int s = 64; s > 0; s >>= 1){
        if (tid < s){
            if (sv[tid+s] > sv[tid] || (sv[tid+s] == sv[tid] && si[tid+s] < si[tid])){
                sv[tid] = sv[tid+s]; si[tid] = si[tid+s];
            }
        }
        __syncthreads();
    }
    if (tid == 0){ g_nodemax[b*384+i] = sv[0]; g_nodeidx[b*384+i] = si[0]; }
}

// ---------------- sort / unm / dst (frozen, passing) ----------------
__global__ void k_sort(int n){
    int b = blockIdx.x, tid = threadIdx.x, npad = blockDim.x;
    extern __shared__ float smemf[];
    float* v  = smemf;
    int*   id = (int*)(smemf + npad);
    v[tid]  = (tid < n) ? g_nodemax[b*384+tid] : -3.4e38f;
    id[tid] = (tid < n) ? tid : 0x7fffffff;
    __syncthreads();
    for (int k = 2; k <= npad; k <<= 1){
        for (int j = k >> 1; j > 0; j >>= 1){
            int ixj = tid ^ j;
            if (ixj > tid){
                bool up = ((tid & k) == 0);
                bool before = (v[tid] > v[ixj]) || (v[tid] == v[ixj] && id[tid] < id[ixj]);
                if (up ? !before : before){
                    float tv = v[tid]; v[tid] = v[ixj]; v[ixj] = tv;
                    int   ti = id[tid]; id[tid] = id[ixj]; id[ixj] = ti;
                }
            }
            __syncthreads();
        }
    }
    if (tid < n) g_edgeidx[b*384+tid] = id[tid];
}

__global__ void k_unm(int ssel, int dsel, int t, int tn, int r, int unm){
    int bid = blockIdx.x;
    int b = bid / unm, u = bid % unm;
    int e = g_edgeidx[b*384 + r + u];
    const float* xs = xbuf(ssel) + ((long)b*t + 2*e)*CC;
    float*       xd = xbuf(dsel) + ((long)b*tn + u)*CC;
    float s = sbuf(ssel)[(long)b*t + 2*e];
    for (int d = threadIdx.x; d < CC; d += blockDim.x)
        xd[d] = __fdiv_rn(__fmul_rn(xs[d], s), s);
    if (threadIdx.x == 0) sbuf(dsel)[(long)b*tn + u] = s;
}

__global__ void k_dst(int ssel, int dsel, int t, int tn, int nb, int r, int unm){
    int bid = blockIdx.x;
    int b = bid / nb, j = bid % nb;
    __shared__ int   se[368];
    __shared__ int   sn[368];
    __shared__ int   match[368];
    __shared__ float msz[368];
    __shared__ int   nm;
    __shared__ float tsz, osz;
    const float* ss = sbuf(ssel) + (long)b*t;
    for (int k = threadIdx.x; k < r; k += blockDim.x){
        int s = g_edgeidx[b*384+k];
        se[k] = s;
        sn[k] = g_nodeidx[b*384+s];
    }
    __syncthreads();
    if (threadIdx.x == 0){
        int c = 0;
        float os = ss[2*j+1];
        float ts = os;
        for (int k = 0; k < r; k++){
            if (sn[k] == j){
                int s = se[k];
                float sz = ss[2*s];
                match[c] = s; msz[c] = sz;
                ts = __fadd_rn(ts, sz);
                c++;
            }
        }
        nm = c; tsz = ts; osz = os;
    }
    __syncthreads();
    const float* xs = xbuf(ssel) + (long)b*t*CC;
    float*       xd = xbuf(dsel) + ((long)b*tn + unm + j)*CC;
    int lnm = nm; float ltsz = tsz, losz = osz;
    for (int d = threadIdx.x; d < CC; d += blockDim.x){
        float acc = __fmul_rn(xs[(long)(2*j+1)*CC + d], losz);
        for (int m = 0; m < lnm; m++)
            acc = __fadd_rn(acc, __fmul_rn(xs[(long)(2*match[m])*CC + d], msz[m]));
        xd[d] = __fdiv_rn(acc, ltsz);
    }
    if (threadIdx.x == 0) sbuf(dsel)[(long)b*tn + unm + j] = ltsz;
}

// ---------------- prep: quantize merged x to fp16 ----------------
__global__ void k_splitx(){
    long i = (long)blockIdx.x * blockDim.x + threadIdx.x;
    const long n = (long)MROWS*CC;
    if (i < n) g_a1[i] = f16q(g_xb[i]);
}

// ---------------- prep: transpose+split weights W[K,N] -> Bh/Bl [N,K] (fp16 limbs) ----
__global__ void k_splitw(const float* __restrict__ W,
                         unsigned short* __restrict__ Bh, unsigned short* __restrict__ Bl,
                         int K, int N){
    __shared__ float tile[32][33];
    int kb = blockIdx.y*32, nb = blockIdx.x*32;
    int tx = threadIdx.x & 31, ty = threadIdx.x >> 5;
    for (int i = ty; i < 32; i += 8)
        tile[i][tx] = W[(long)(kb+i)*N + nb + tx];
    __syncthreads();
    for (int i = ty; i < 32; i += 8){
        float v = tile[tx][i];
        unsigned short h, l;
        f16split2(v, h, l);
        long o = (long)(nb+i)*K + kb + tx;
        Bh[o] = h; Bl[o] = l;
    }
}

// ---------------- HMMA fp16x2 GEMM (portable mma.sync) ----------------
// C[M,N] = A[M,K] x B[N,K]^T ; A single fp16, B fp16 hi/lo; f32 accum.
// C = A*Bh + A*Bl  (2 mma per tile). CTA 128x128, K-chunk 32, 3-stage cp.async.
// 8 warps 2(M)x4(N); warp 64x32 = 4x4 m16n8k16 tiles.
// SMEM rows padded to 40 halves (80B) -> conflict-free ldmatrix.
#define RS      40
#define TILE_B  (128*RS*2)      // 10240 bytes per operand array
#define BUF_B   (3*TILE_B)      // A, Bh, Bl
#define NSTAGE  3
#define GSMEM   (NSTAGE*BUF_B)  // 92160 bytes

template<int DO_GELU>
__global__ __launch_bounds__(256, 2) void k_mmagemm(
    const unsigned short* __restrict__ A,
    const unsigned short* __restrict__ Bh, const unsigned short* __restrict__ Bl,
    const float* __restrict__ bias, int K,
    float* __restrict__ Cf, unsigned short* __restrict__ C2)
{
    extern __shared__ char smemc[];
    uint32_t sb = smem_u32(smemc);
    int tid = threadIdx.x, lane = tid & 31, wid = tid >> 5;
    int wm = wid & 1, wn = wid >> 1;
    long m0 = (long)blockIdx.y*128, n0 = (long)blockIdx.x*128;
    int nc = K / 32;

    float acc[4][4][4];
    #pragma unroll
    for (int a = 0; a < 4; a++)
        #pragma unroll
        for (int b = 0; b < 4; b++)
            #pragma unroll
            for (int c = 0; c < 4; c++) acc[a][b][c] = 0.f;

    const unsigned short* srcs[3] = {A, Bh, Bl};
    long r0s[3]; r0s[0] = m0; r0s[1] = n0; r0s[2] = n0;

    auto load_buf = [&](int buf, int c){
        int k0 = c * 32;
        uint32_t base = sb + buf*BUF_B;
        #pragma unroll
        for (int a = 0; a < 3; a++){
            #pragma unroll
            for (int i = 0; i < 2; i++){
                int idx = tid + i*256;            // 0..511
                int row = idx >> 2, g = idx & 3;  // 128 rows x 4 granules(8 halves)
                uint32_t dst = base + a*TILE_B + row*80 + g*16;
                cp16(dst, srcs[a] + (r0s[a]+row)*(long)K + k0 + g*8);
            }
        }
    };

    auto comp = [&](int buf){
        uint32_t base   = sb + buf*BUF_B;
        uint32_t baseA  = base;
        uint32_t baseBh = base + TILE_B, baseBl = base + 2*TILE_B;
        #pragma unroll
        for (int ks = 0; ks < 2; ks++){
            uint32_t bh[4][2], bl[4][2];
            int bn8 = lane & 7, bg = (lane >> 3) & 1;
            #pragma unroll
            for (int ni = 0; ni < 4; ni++){
                int nrow = wn*32 + ni*8 + bn8;
                uint32_t ab = nrow*80 + (ks*2 + bg)*16;
                ldsm_x2(bh[ni][0], bh[ni][1], baseBh + ab);
                ldsm_x2(bl[ni][0], bl[ni][1], baseBl + ab);
            }
            #pragma unroll
            for (int mi = 0; mi < 4; mi++){
                int arow = wm*64 + mi*16 + (lane & 15);
                int ag = ks*2 + (lane >> 4);
                uint32_t aoff = arow*80 + ag*16;
                uint32_t a_f[4];
                ldsm_x4(a_f[0], a_f[1], a_f[2], a_f[3], baseA + aoff);
                #pragma unroll
                for (int ni = 0; ni < 4; ni++){
                    mma16816h(acc[mi][ni], a_f, bh[ni]);
                    mma16816h(acc[mi][ni], a_f, bl[ni]);
                }
            }
        }
    };

    load_buf(0, 0); CP_COMMIT();
    load_buf(1, 1); CP_COMMIT();
    for (int c = 0; c < nc; c++){
        if (c + 1 < nc){ CP_WAIT(1); } else { CP_WAIT(0); }
        __syncthreads();
        comp(c % NSTAGE);
        if (c + 2 < nc){ load_buf((c+2) % NSTAGE, c+2); CP_COMMIT(); }
    }

    // epilogue: m16n8k16 d mapping: row = l/4 + (r>=2)*8; col = (l%4)*2 + (r&1)
    #pragma unroll
    for (int mi = 0; mi < 4; mi++){
        #pragma unroll
        for (int ni = 0; ni < 4; ni++){
            #pragma unroll
            for (int r = 0; r < 4; r++){
                long m = m0 + wm*64 + mi*16 + (lane >> 2) + ((r >> 1) << 3);
                long n = n0 + wn*32 + ni*8  + ((lane & 3) << 1) + (r & 1);
                float v = __fadd_rn(acc[mi][ni][r], __ldg(bias + n));
                if (DO_GELU){
                    v = 0.5f*v*(1.0f + erff(v*0.70710678118654752f));
                    C2[m*HH + n] = f16q(v);
                } else {
                    Cf[m*HH + n] = v;
                }
            }
        }
    }
}

// ---------------- launcher ----------------
extern "C" void kernel_launch(void* const* d_in, const int* in_sizes, int n_in,
                              void* d_out, int out_size){
    const float* x   = (const float*)d_in[0];
    const float* pos = (const float*)d_in[1];
    const float* w1  = (const float*)d_in[2];
    const float* b1  = (const float*)d_in[3];
    const float* w2  = (const float*)d_in[4];
    const float* b2  = (const float*)d_in[5];
    float* out = (float*)d_out;

    void *p_a1, *p_a2, *p_b1h, *p_b1l, *p_b2h, *p_b2l;
    cudaGetSymbolAddress(&p_a1, g_a1);   cudaGetSymbolAddress(&p_a2, g_a2);
    cudaGetSymbolAddress(&p_b1h, g_b1h); cudaGetSymbolAddress(&p_b1l, g_b1l);
    cudaGetSymbolAddress(&p_b2h, g_b2h); cudaGetSymbolAddress(&p_b2l, g_b2l);

    cudaFuncSetAttribute(k_mmagemm<1>, cudaFuncAttributeMaxDynamicSharedMemorySize, GSMEM);
    cudaFuncSetAttribute(k_mmagemm<0>, cudaFuncAttributeMaxDynamicSharedMemorySize, GSMEM);

    {
        long n = (long)BB*P0*CC;
        k_addpos<<<(unsigned)((n + 255)/256), 256>>>(x, pos);
        k_initsize<<<(BB*P0 + 255)/256, 256>>>();
    }

    // weight prep (independent of merges)
    k_splitw<<<dim3(HH/32, CC/32), 256>>>(w1, (unsigned short*)p_b1h, (unsigned short*)p_b1l, CC, HH);
    k_splitw<<<dim3(HH/32, HH/32), 256>>>(w2, (unsigned short*)p_b2h, (unsigned short*)p_b2l, HH, HH);

    // merge schedule: 729 -> 365 -> 183 -> 128, r = {364, 182, 55}
    const int T[4] = {729, 365, 183, 128};
    const int R[3] = {364, 182, 55};
    int ssel = 0;
    for (int it = 0; it < 3; it++){
        int t = T[it], tn = T[it+1];
        int na = (t + 1) / 2, nb = t / 2;
        int r = R[it], unm = na - r;
        int dsel = 1 - ssel;
        int npad = 1; while (npad < na) npad <<= 1;

        k_metric<<<(BB*t + 3)/4, 128>>>(ssel, t);
        k_scores<<<BB*na, 128>>>(t, na, nb);
        k_sort<<<BB, npad, npad*8>>>(na);
        k_unm<<<BB*unm, 128>>>(ssel, dsel, t, tn, r, unm);
        k_dst<<<BB*nb, 128>>>(ssel, dsel, t, tn, nb, r, unm);
        ssel = dsel;
    }
    // merged tokens now in g_xb (64x128x1152)

    {
        long n = (long)MROWS*CC;
        k_splitx<<<(unsigned)((n + 255)/256), 256>>>();
    }

    dim3 gg(HH/128, MROWS/128);   // 28 x 64
    k_mmagemm<1><<<gg, 256, GSMEM>>>(
        (const unsigned short*)p_a1,
        (const unsigned short*)p_b1h, (const unsigned short*)p_b1l,
        b1, CC, nullptr, (unsigned short*)p_a2);
    k_mmagemm<0><<<gg, 256, GSMEM>>>(
        (const unsigned short*)p_a2,
        (const unsigned short*)p_b2h, (const unsigned short*)p_b2l,
        b2, HH, out, nullptr);
}

// round 14
// speedup vs baseline: 2.4487x; 1.1637x over previous
#include <cuda_runtime.h>
#include <cuda_bf16.h>
#include <cuda_fp16.h>
#include <math.h>
#include <stdint.h>

// ---------------- problem constants ----------------
#define BB    64
#define P0    729
#define CC    1152
#define HH    3584
#define HEADS 16
#define HD    72
#define TT    128
#define MROWS (BB*TT)     // 8192

// ---------------- scratch (device globals) ----------------
__device__ float g_xa[BB*P0*CC];
__device__ float g_xb[BB*P0*CC];
__device__ float g_sa[BB*P0];
__device__ float g_sb[BB*P0];
__device__ float g_metric[BB*P0*HD];
__device__ float g_nodemax[BB*384];
__device__ int   g_nodeidx[BB*384];
__device__ int   g_edgeidx[BB*384];
// fp16 operand buffers for tensor-core GEMMs
__device__ __align__(16) unsigned short g_a1[(long)MROWS*CC];     // A1 fp16
__device__ __align__(16) unsigned short g_a2[(long)MROWS*HH];     // A2 fp16 (gelu out)
__device__ __align__(16) unsigned short g_b1[(long)HH*CC];        // W1^T fp16
__device__ __align__(16) unsigned short g_b2[(long)HH*HH];        // W2^T fp16

__device__ __forceinline__ float* xbuf(int s){ return s ? g_xb : g_xa; }
__device__ __forceinline__ float* sbuf(int s){ return s ? g_sb : g_sa; }

// ---------------- portable PTX helpers (sm_80+) ----------------
__device__ __forceinline__ uint32_t smem_u32(const void* p){
    uint32_t a;
    asm("{ .reg .u64 t; cvta.to.shared.u64 t, %1; cvt.u32.u64 %0, t; }" : "=r"(a) : "l"(p));
    return a;
}
__device__ __forceinline__ void cp16(uint32_t dst, const void* src){
    asm volatile("cp.async.cg.shared.global [%0], [%1], 16;" :: "r"(dst), "l"(src) : "memory");
}
#define CP_COMMIT() asm volatile("cp.async.commit_group;" ::: "memory")
#define CP_WAIT(n)  asm volatile("cp.async.wait_group %0;" :: "n"(n) : "memory")

__device__ __forceinline__ void ldsm_x4(uint32_t& r0, uint32_t& r1, uint32_t& r2, uint32_t& r3, uint32_t addr){
    asm volatile("ldmatrix.sync.aligned.m8n8.x4.shared.b16 {%0,%1,%2,%3}, [%4];"
        : "=r"(r0), "=r"(r1), "=r"(r2), "=r"(r3) : "r"(addr));
}
__device__ __forceinline__ void ldsm_x2(uint32_t& r0, uint32_t& r1, uint32_t addr){
    asm volatile("ldmatrix.sync.aligned.m8n8.x2.shared.b16 {%0,%1}, [%2];"
        : "=r"(r0), "=r"(r1) : "r"(addr));
}
__device__ __forceinline__ void mma16816h(float* d, const uint32_t* a, const uint32_t* b){
    asm volatile("mma.sync.aligned.m16n8k16.row.col.f32.f16.f16.f32 "
        "{%0,%1,%2,%3}, {%4,%5,%6,%7}, {%8,%9}, {%0,%1,%2,%3};"
        : "+f"(d[0]), "+f"(d[1]), "+f"(d[2]), "+f"(d[3])
        : "r"(a[0]), "r"(a[1]), "r"(a[2]), "r"(a[3]), "r"(b[0]), "r"(b[1]));
}

__device__ __forceinline__ unsigned short f16q(float a){
    __half h = __float2half_rn(a);
    return *(unsigned short*)&h;
}
// 3-way bf16 (decision scores; BF16x9 reference model — FROZEN)
__device__ __forceinline__ void bf16split3(float a, float& h, float& m, float& l){
    h = __bfloat162float(__float2bfloat16_rn(a));
    float r1 = __fadd_rn(a, -h);
    m = __bfloat162float(__float2bfloat16_rn(r1));
    float r2 = __fadd_rn(r1, -m);
    l = __bfloat162float(__float2bfloat16_rn(r2));
}

// ---------------- elementwise ----------------
__global__ void k_addpos(const float* __restrict__ x, const float* __restrict__ pos){
    long i = (long)blockIdx.x * blockDim.x + threadIdx.x;
    const long n = (long)BB*P0*CC;
    if (i < n){
        int pc = (int)(i % ((long)P0*CC));
        g_xa[i] = __fadd_rn(x[i], pos[pc]);
    }
}
__global__ void k_initsize(){
    int i = blockIdx.x*blockDim.x + threadIdx.x;
    if (i < BB*P0) g_sa[i] = 1.0f;
}

// ---------------- metric (frozen, passing) ----------------
__global__ void k_metric(int ssel, int t){
    int gw = blockIdx.x*4 + (threadIdx.x >> 5);
    if (gw >= BB*t) return;
    int lane = threadIdx.x & 31;
    const float* x = xbuf(ssel) + (long)gw*CC;
    float m0 = 0.f, m1 = 0.f, m2 = 0.f;
    #pragma unroll
    for (int h = 0; h < HEADS; h++){
        m0 = __fadd_rn(m0, x[h*HD + lane]);
        m1 = __fadd_rn(m1, x[h*HD + lane + 32]);
    }
    m0 = __fmul_rn(m0, 0.0625f);
    m1 = __fmul_rn(m1, 0.0625f);
    if (lane < 8){
        #pragma unroll
        for (int h = 0; h < HEADS; h++) m2 = __fadd_rn(m2, x[h*HD + lane + 64]);
        m2 = __fmul_rn(m2, 0.0625f);
    }
    float acc = __fmaf_rn(m0, m0, 0.0f);
    acc = __fmaf_rn(m1, m1, acc);
    if (lane < 8) acc = __fmaf_rn(m2, m2, acc);
    #pragma unroll
    for (int off = 16; off > 0; off >>= 1)
        acc = __fadd_rn(acc, __shfl_down_sync(0xffffffffu, acc, off));
    float nrm = __fsqrt_rn(__shfl_sync(0xffffffffu, acc, 0));
    float* Mo = g_metric + (long)gw*HD;
    Mo[lane]      = __fdiv_rn(m0, nrm);
    Mo[lane + 32] = __fdiv_rn(m1, nrm);
    if (lane < 8) Mo[lane + 64] = __fdiv_rn(m2, nrm);
}

// ---------------- scores: BF16x9-emulated dot (frozen, passing) ----------------
__global__ void k_scores(int t, int na, int nb){
    int bid = blockIdx.x;
    int b = bid / na, i = bid % na;
    const float* M = g_metric + (long)b*t*HD;
    __shared__ float ah[HD], am[HD], al[HD];
    int tid = threadIdx.x;
    if (tid < HD){
        float av = M[(long)(2*i)*HD + tid];
        float h, m, l; bf16split3(av, h, m, l);
        ah[tid] = h; am[tid] = m; al[tid] = l;
    }
    __syncthreads();
    float bv = -2.0f; int bi = 0x7fffffff;
    for (int j = tid; j < nb; j += blockDim.x){
        const float* br = M + (long)(2*j+1)*HD;
        float s_ll=0.f,s_lm=0.f,s_ml=0.f,s_lh=0.f,s_mm=0.f,s_hl=0.f,s_mh=0.f,s_hm=0.f,s_hh=0.f;
        #pragma unroll 8
        for (int k = 0; k < HD; k++){
            float bh, bm, bl; bf16split3(br[k], bh, bm, bl);
            float Ah = ah[k], Am = am[k], Al = al[k];
            s_ll = __fmaf_rn(Al, bl, s_ll);
            s_lm = __fmaf_rn(Al, bm, s_lm);
            s_ml = __fmaf_rn(Am, bl, s_ml);
            s_lh = __fmaf_rn(Al, bh, s_lh);
            s_mm = __fmaf_rn(Am, bm, s_mm);
            s_hl = __fmaf_rn(Ah, bl, s_hl);
            s_mh = __fmaf_rn(Am, bh, s_mh);
            s_hm = __fmaf_rn(Ah, bm, s_hm);
            s_hh = __fmaf_rn(Ah, bh, s_hh);
        }
        float acc = s_ll;
        acc = __fadd_rn(acc, s_lm);
        acc = __fadd_rn(acc, s_ml);
        acc = __fadd_rn(acc, s_lh);
        acc = __fadd_rn(acc, s_mm);
        acc = __fadd_rn(acc, s_hl);
        acc = __fadd_rn(acc, s_mh);
        acc = __fadd_rn(acc, s_hm);
        acc = __fadd_rn(acc, s_hh);
        if (acc > bv){ bv = acc; bi = j; }
    }
    __shared__ float sv[128]; __shared__ int si[128];
    sv[tid] = bv; si[tid] = bi;
    __syncthreads();
    for (int s = 64; s > 0; s >>= 1){
        if (tid < s){
            if (sv[tid+s] > sv[tid] || (sv[tid+s] == sv[tid] && si[tid+s] < si[tid])){
                sv[tid] = sv[tid+s]; si[tid] = si[tid+s];
            }
        }
        __syncthreads();
    }
    if (tid == 0){ g_nodemax[b*384+i] = sv[0]; g_nodeidx[b*384+i] = si[0]; }
}

// ---------------- sort / unm / dst (frozen, passing) ----------------
__global__ void k_sort(int n){
    int b = blockIdx.x, tid = threadIdx.x, npad = blockDim.x;
    extern __shared__ float smemf[];
    float* v  = smemf;
    int*   id = (int*)(smemf + npad);
    v[tid]  = (tid < n) ? g_nodemax[b*384+tid] : -3.4e38f;
    id[tid] = (tid < n) ? tid : 0x7fffffff;
    __syncthreads();
    for (int k = 2; k <= npad; k <<= 1){
        for (int j = k >> 1; j > 0; j >>= 1){
            int ixj = tid ^ j;
            if (ixj > tid){
                bool up = ((tid & k) == 0);
                bool before = (v[tid] > v[ixj]) || (v[tid] == v[ixj] && id[tid] < id[ixj]);
                if (up ? !before : before){
                    float tv = v[tid]; v[tid] = v[ixj]; v[ixj] = tv;
                    int   ti = id[tid]; id[tid] = id[ixj]; id[ixj] = ti;
                }
            }
            __syncthreads();
        }
    }
    if (tid < n) g_edgeidx[b*384+tid] = id[tid];
}

__global__ void k_unm(int ssel, int dsel, int t, int tn, int r, int unm){
    int bid = blockIdx.x;
    int b = bid / unm, u = bid % unm;
    int e = g_edgeidx[b*384 + r + u];
    const float* xs = xbuf(ssel) + ((long)b*t + 2*e)*CC;
    float*       xd = xbuf(dsel) + ((long)b*tn + u)*CC;
    float s = sbuf(ssel)[(long)b*t + 2*e];
    for (int d = threadIdx.x; d < CC; d += blockDim.x)
        xd[d] = __fdiv_rn(__fmul_rn(xs[d], s), s);
    if (threadIdx.x == 0) sbuf(dsel)[(long)b*tn + u] = s;
}

__global__ void k_dst(int ssel, int dsel, int t, int tn, int nb, int r, int unm){
    int bid = blockIdx.x;
    int b = bid / nb, j = bid % nb;
    __shared__ int   se[368];
    __shared__ int   sn[368];
    __shared__ int   match[368];
    __shared__ float msz[368];
    __shared__ int   nm;
    __shared__ float tsz, osz;
    const float* ss = sbuf(ssel) + (long)b*t;
    for (int k = threadIdx.x; k < r; k += blockDim.x){
        int s = g_edgeidx[b*384+k];
        se[k] = s;
        sn[k] = g_nodeidx[b*384+s];
    }
    __syncthreads();
    if (threadIdx.x == 0){
        int c = 0;
        float os = ss[2*j+1];
        float ts = os;
        for (int k = 0; k < r; k++){
            if (sn[k] == j){
                int s = se[k];
                float sz = ss[2*s];
                match[c] = s; msz[c] = sz;
                ts = __fadd_rn(ts, sz);
                c++;
            }
        }
        nm = c; tsz = ts; osz = os;
    }
    __syncthreads();
    const float* xs = xbuf(ssel) + (long)b*t*CC;
    float*       xd = xbuf(dsel) + ((long)b*tn + unm + j)*CC;
    int lnm = nm; float ltsz = tsz, losz = osz;
    for (int d = threadIdx.x; d < CC; d += blockDim.x){
        float acc = __fmul_rn(xs[(long)(2*j+1)*CC + d], losz);
        for (int m = 0; m < lnm; m++)
            acc = __fadd_rn(acc, __fmul_rn(xs[(long)(2*match[m])*CC + d], msz[m]));
        xd[d] = __fdiv_rn(acc, ltsz);
    }
    if (threadIdx.x == 0) sbuf(dsel)[(long)b*tn + unm + j] = ltsz;
}

// ---------------- prep: quantize merged x to fp16 ----------------
__global__ void k_splitx(){
    long i = (long)blockIdx.x * blockDim.x + threadIdx.x;
    const long n = (long)MROWS*CC;
    if (i < n) g_a1[i] = f16q(g_xb[i]);
}

// ---------------- prep: transpose+quantize weights W[K,N] -> B[N,K] fp16 ----------------
__global__ void k_splitw(const float* __restrict__ W,
                         unsigned short* __restrict__ Bq, int K, int N){
    __shared__ float tile[32][33];
    int kb = blockIdx.y*32, nb = blockIdx.x*32;
    int tx = threadIdx.x & 31, ty = threadIdx.x >> 5;
    for (int i = ty; i < 32; i += 8)
        tile[i][tx] = W[(long)(kb+i)*N + nb + tx];
    __syncthreads();
    for (int i = ty; i < 32; i += 8){
        long o = (long)(nb+i)*K + kb + tx;
        Bq[o] = f16q(tile[tx][i]);
    }
}

// ---------------- fp16 HMMA GEMM (portable mma.sync) ----------------
// C[M,N] = A[M,K] x B[N,K]^T ; single fp16 operands, f32 accum.
// CTA 128x128, K-chunk 64, 3-stage cp.async ring; 8 warps 2(M)x4(N),
// warp tile 64x32 = 4x4 m16n8k16.  SMEM rows padded to 72 halves (144B):
// ldmatrix bank index (36r+4g) mod 32 -> conflict-free.
#define RS      72
#define TILE_B  (128*RS*2)      // 18432 bytes per operand array
#define BUF_B   (2*TILE_B)      // A, B
#define NSTAGE  3
#define GSMEM   (NSTAGE*BUF_B)  // 110592 bytes

template<int DO_GELU>
__global__ __launch_bounds__(256, 2) void k_mmagemm(
    const unsigned short* __restrict__ A,
    const unsigned short* __restrict__ B,
    const float* __restrict__ bias, int K,
    float* __restrict__ Cf, unsigned short* __restrict__ C2)
{
    extern __shared__ char smemc[];
    uint32_t sb = smem_u32(smemc);
    int tid = threadIdx.x, lane = tid & 31, wid = tid >> 5;
    int wm = wid & 1, wn = wid >> 1;
    long m0 = (long)blockIdx.y*128, n0 = (long)blockIdx.x*128;
    int nc = K / 64;

    float acc[4][4][4];
    #pragma unroll
    for (int a = 0; a < 4; a++)
        #pragma unroll
        for (int b = 0; b < 4; b++)
            #pragma unroll
            for (int c = 0; c < 4; c++) acc[a][b][c] = 0.f;

    const unsigned short* srcs[2] = {A, B};
    long r0s[2]; r0s[0] = m0; r0s[1] = n0;

    auto load_buf = [&](int buf, int c){
        int k0 = c * 64;
        uint32_t base = sb + buf*BUF_B;
        #pragma unroll
        for (int a = 0; a < 2; a++){
            #pragma unroll
            for (int i = 0; i < 4; i++){
                int idx = tid + i*256;            // 0..1023
                int row = idx >> 3, g = idx & 7;  // 128 rows x 8 granules(8 halves)
                uint32_t dst = base + a*TILE_B + row*144 + g*16;
                cp16(dst, srcs[a] + (r0s[a]+row)*(long)K + k0 + g*8);
            }
        }
    };

    auto comp = [&](int buf){
        uint32_t base  = sb + buf*BUF_B;
        uint32_t baseA = base, baseB = base + TILE_B;
        #pragma unroll
        for (int ks = 0; ks < 4; ks++){
            uint32_t bfr[4][2];
            int bn8 = lane & 7, bg = (lane >> 3) & 1;
            #pragma unroll
            for (int ni = 0; ni < 4; ni++){
                int nrow = wn*32 + ni*8 + bn8;
                ldsm_x2(bfr[ni][0], bfr[ni][1], baseB + nrow*144 + (ks*2 + bg)*16);
            }
            #pragma unroll
            for (int mi = 0; mi < 4; mi++){
                int arow = wm*64 + mi*16 + (lane & 15);
                int ag = ks*2 + (lane >> 4);
                uint32_t a_f[4];
                ldsm_x4(a_f[0], a_f[1], a_f[2], a_f[3], baseA + arow*144 + ag*16);
                #pragma unroll
                for (int ni = 0; ni < 4; ni++)
                    mma16816h(acc[mi][ni], a_f, bfr[ni]);
            }
        }
    };

    load_buf(0, 0); CP_COMMIT();
    load_buf(1, 1); CP_COMMIT();
    for (int c = 0; c < nc; c++){
        if (c + 1 < nc){ CP_WAIT(1); } else { CP_WAIT(0); }
        __syncthreads();
        comp(c % NSTAGE);
        if (c + 2 < nc){ load_buf((c+2) % NSTAGE, c+2); CP_COMMIT(); }
    }

    // epilogue: m16n8k16 d mapping: row = l/4 + (r>=2)*8; col = (l%4)*2 + (r&1)
    #pragma unroll
    for (int mi = 0; mi < 4; mi++){
        #pragma unroll
        for (int ni = 0; ni < 4; ni++){
            #pragma unroll
            for (int r = 0; r < 4; r++){
                long m = m0 + wm*64 + mi*16 + (lane >> 2) + ((r >> 1) << 3);
                long n = n0 + wn*32 + ni*8  + ((lane & 3) << 1) + (r & 1);
                float v = __fadd_rn(acc[mi][ni][r], __ldg(bias + n));
                if (DO_GELU){
                    v = 0.5f*v*(1.0f + erff(v*0.70710678118654752f));
                    C2[m*HH + n] = f16q(v);
                } else {
                    Cf[m*HH + n] = v;
                }
            }
        }
    }
}

// ---------------- launcher ----------------
extern "C" void kernel_launch(void* const* d_in, const int* in_sizes, int n_in,
                              void* d_out, int out_size){
    const float* x   = (const float*)d_in[0];
    const float* pos = (const float*)d_in[1];
    const float* w1  = (const float*)d_in[2];
    const float* b1  = (const float*)d_in[3];
    const float* w2  = (const float*)d_in[4];
    const float* b2  = (const float*)d_in[5];
    float* out = (float*)d_out;

    void *p_a1, *p_a2, *p_b1, *p_b2;
    cudaGetSymbolAddress(&p_a1, g_a1); cudaGetSymbolAddress(&p_a2, g_a2);
    cudaGetSymbolAddress(&p_b1, g_b1); cudaGetSymbolAddress(&p_b2, g_b2);

    cudaFuncSetAttribute(k_mmagemm<1>, cudaFuncAttributeMaxDynamicSharedMemorySize, GSMEM);
    cudaFuncSetAttribute(k_mmagemm<0>, cudaFuncAttributeMaxDynamicSharedMemorySize, GSMEM);

    {
        long n = (long)BB*P0*CC;
        k_addpos<<<(unsigned)((n + 255)/256), 256>>>(x, pos);
        k_initsize<<<(BB*P0 + 255)/256, 256>>>();
    }

    // weight prep (independent of merges)
    k_splitw<<<dim3(HH/32, CC/32), 256>>>(w1, (unsigned short*)p_b1, CC, HH);
    k_splitw<<<dim3(HH/32, HH/32), 256>>>(w2, (unsigned short*)p_b2, HH, HH);

    // merge schedule: 729 -> 365 -> 183 -> 128, r = {364, 182, 55}
    const int T[4] = {729, 365, 183, 128};
    const int R[3] = {364, 182, 55};
    int ssel = 0;
    for (int it = 0; it < 3; it++){
        int t = T[it], tn = T[it+1];
        int na = (t + 1) / 2, nb = t / 2;
        int r = R[it], unm = na - r;
        int dsel = 1 - ssel;
        int npad = 1; while (npad < na) npad <<= 1;

        k_metric<<<(BB*t + 3)/4, 128>>>(ssel, t);
        k_scores<<<BB*na, 128>>>(t, na, nb);
        k_sort<<<BB, npad, npad*8>>>(na);
        k_unm<<<BB*unm, 128>>>(ssel, dsel, t, tn, r, unm);
        k_dst<<<BB*nb, 128>>>(ssel, dsel, t, tn, nb, r, unm);
        ssel = dsel;
    }
    // merged tokens now in g_xb (64x128x1152)

    {
        long n = (long)MROWS*CC;
        k_splitx<<<(unsigned)((n + 255)/256), 256>>>();
    }

    dim3 gg(HH/128, MROWS/128);   // 28 x 64
    k_mmagemm<1><<<gg, 256, GSMEM>>>(
        (const unsigned short*)p_a1, (const unsigned short*)p_b1,
        b1, CC, nullptr, (unsigned short*)p_a2);
    k_mmagemm<0><<<gg, 256, GSMEM>>>(
        (const unsigned short*)p_a2, (const unsigned short*)p_b2,
        b2, HH, out, nullptr);
}